// round 6
// baseline (speedup 1.0000x reference)
#include <cuda_runtime.h>

// BoxQueryAndGroup: B=4, N=16384, C=64, NQ=256, S=32
//
// Reference: idx_f = in_box * arange(N); stable argsort ascending, first 32.
// Zero-keys = {n : !in_box[n]} ∪ {0}; the answer is the 32 smallest indices
// with (n==0 || !in_box), ascending. Fallback loops keep exact argsort
// semantics if fewer than 32 zero-keys exist (never observed).
// local_group_mask is identically False => 0.0f.
//
// Outputs concatenated flat, float32:
//   grouped_xyz (B,3,NQ,S), new_features (B,67,NQ,S), mask (B,NQ,S)
//
// R5: R4 structure (warp0 unrolled 64-pt scan -> smem -> barrier; all-warp
// STG.128 output) + feature hot-set PREFETCH overlapped with the scan to
// remove the post-barrier DRAM-dependent gather level.

#define BQ_B  4
#define BQ_N  16384
#define BQ_C  64
#define BQ_NQ 256
#define BQ_S  32

#define BQ_THREADS 256

__device__ __forceinline__ void prefetch_l1(const void* p) {
    asm volatile("prefetch.global.L1 [%0];" :: "l"(p));
}

__global__ __launch_bounds__(BQ_THREADS)
void boxquery_group_kernel(const float* __restrict__ key_xyz,     // (B,N,3)
                           const float* __restrict__ key_feat,    // (B,C,N)
                           const float* __restrict__ query_box,   // (B,NQ,6)
                           float* __restrict__ out) {
    const int lane = threadIdx.x & 31;
    const int role = threadIdx.x >> 5;          // warp id == role 0..7
    const int qid  = blockIdx.x;                // b*NQ + q
    const int b    = qid >> 8;
    const int q    = qid & (BQ_NQ - 1);

    __shared__ int s_idx[BQ_S];

    const float* qb = query_box + (size_t)qid * 6;
    const float* xyzb = key_xyz + (size_t)b * BQ_N * 3;
    const float* fb = key_feat + (size_t)b * BQ_C * BQ_N;
    const int c0ch = role * 8;

    // ---- Prefetch the feature hot set (idx < 64 covers all realistic
    //      selections) in parallel with the scan. 2 lines per channel. ----
    if (lane < 16) {
        const int c   = c0ch + (lane >> 1);
        const int off = (lane & 1) << 5;        // 0 or 32 floats = 0/128 B
        prefetch_l1(fb + (size_t)c * BQ_N + off);
    }

    const float cx = qb[0], cy = qb[1], cz = qb[2];
    const float hx = 0.5f * qb[3], hy = 0.5f * qb[4], hz = 0.5f * qb[5];

    // ---- Selection: warp 0 only, unrolled 64-point fast path ----
    if (role == 0) {
        s_idx[lane] = 0;
        __syncwarp();

        const int n1 = lane + 32;
        const float x0 = xyzb[lane * 3 + 0];
        const float y0 = xyzb[lane * 3 + 1];
        const float z0 = xyzb[lane * 3 + 2];
        const float x1 = xyzb[n1 * 3 + 0];
        const float y1 = xyzb[n1 * 3 + 1];
        const float z1 = xyzb[n1 * 3 + 2];

        const bool inb0 = (fabsf(x0 - cx) <= hx) && (fabsf(y0 - cy) <= hy) &&
                          (fabsf(z0 - cz) <= hz);
        const bool inb1 = (fabsf(x1 - cx) <= hx) && (fabsf(y1 - cy) <= hy) &&
                          (fabsf(z1 - cz) <= hz);
        const bool cand0 = (lane == 0) || !inb0;
        const bool cand1 = !inb1;

        const unsigned m0 = __ballot_sync(0xffffffffu, cand0);
        const unsigned m1 = __ballot_sync(0xffffffffu, cand1);
        const int c0 = __popc(m0);
        const int c1 = __popc(m1);

        int idx = -1;
        if (lane < c0) {
            idx = (int)__fns(m0, 0, lane + 1);
        } else if (lane - c0 < c1) {
            idx = 32 + (int)__fns(m1, 0, lane - c0 + 1);
        }
        if (idx >= 0) s_idx[lane] = idx;

        int count = c0 + c1;
        // Slow continuation (statistically never taken): finish zero-keys.
        if (count < BQ_S) {
            int base = 64;
            while (count < BQ_S && base < BQ_N) {
                const int n = base + lane;
                const float x = xyzb[n * 3 + 0];
                const float y = xyzb[n * 3 + 1];
                const float z = xyzb[n * 3 + 2];
                const bool cand = !((fabsf(x - cx) <= hx) &&
                                    (fabsf(y - cy) <= hy) &&
                                    (fabsf(z - cz) <= hz));
                const unsigned m = __ballot_sync(0xffffffffu, cand);
                const int slot = count + __popc(m & ((1u << lane) - 1u));
                if (cand && slot < BQ_S) s_idx[slot] = n;
                count += __popc(m);
                base  += 32;
            }
            // Pass 2: in-box indices n>0, key=n ascending.
            if (count < BQ_S) {
                base = 0;
                while (count < BQ_S && base < BQ_N) {
                    const int n = base + lane;
                    const float x = xyzb[n * 3 + 0];
                    const float y = xyzb[n * 3 + 1];
                    const float z = xyzb[n * 3 + 2];
                    const bool cand = (n != 0) &&
                                      (fabsf(x - cx) <= hx) &&
                                      (fabsf(y - cy) <= hy) &&
                                      (fabsf(z - cz) <= hz);
                    const unsigned m = __ballot_sync(0xffffffffu, cand);
                    const int slot = count + __popc(m & ((1u << lane) - 1u));
                    if (cand && slot < BQ_S) s_idx[slot] = n;
                    count += __popc(m);
                    base  += 32;
                }
            }
        }
    }
    __syncthreads();

    // ---- Consumers: STG.128-only output ----
    const int j = lane & 7;                 // float4 slot: samples 4j..4j+3
    const int4 iv = ((const int4*)s_idx)[j];
    const int i0 = iv.x, i1 = iv.y, i2 = iv.z, i3 = iv.w;

    float* gxyz = out;                                              // (B,3,NQ,S)
    float* nf   = out + (size_t)BQ_B * 3 * BQ_NQ * BQ_S;            // (B,67,NQ,S)
    float* mask = nf  + (size_t)BQ_B * (3 + BQ_C) * BQ_NQ * BQ_S;   // (B,NQ,S)
    const size_t plane = (size_t)BQ_NQ * BQ_S;
    const size_t qs4   = (size_t)q * BQ_S + 4 * j;

    if (role < 2) {
        const int r = lane >> 3;            // 0=gx 1=gy 2=gz 3=mask
        float4 v = make_float4(0.f, 0.f, 0.f, 0.f);
        if (r < 3) {
            const float cr = (r == 0) ? cx : (r == 1) ? cy : cz;
            v.x = xyzb[i0 * 3 + r] - cr;
            v.y = xyzb[i1 * 3 + r] - cr;
            v.z = xyzb[i2 * 3 + r] - cr;
            v.w = xyzb[i3 * 3 + r] - cr;
        }
        if (role == 0) {
            float* p = (r < 3) ? (gxyz + ((size_t)b * 3 + r) * plane + qs4)
                               : (mask + (size_t)b * plane + qs4);
            *(float4*)p = v;
        } else if (r < 3) {
            *(float4*)(nf + ((size_t)b * (3 + BQ_C) + r) * plane + qs4) = v;
        }
    }

    // Features: 8 channels per warp, 2 STG.128 per warp.
    #pragma unroll
    for (int p = 0; p < 2; p++) {
        const int c = c0ch + p * 4 + (lane >> 3);
        const float* fr = fb + (size_t)c * BQ_N;
        float4 v;
        v.x = __ldg(fr + i0);
        v.y = __ldg(fr + i1);
        v.z = __ldg(fr + i2);
        v.w = __ldg(fr + i3);
        *(float4*)(nf + ((size_t)b * (3 + BQ_C) + 3 + c) * plane + qs4) = v;
    }
}

extern "C" void kernel_launch(void* const* d_in, const int* in_sizes, int n_in,
                              void* d_out, int out_size) {
    const float* key_xyz   = (const float*)d_in[0];
    const float* key_feat  = (const float*)d_in[1];
    const float* query_box = (const float*)d_in[2];
    float* out = (float*)d_out;

    boxquery_group_kernel<<<BQ_B * BQ_NQ, BQ_THREADS>>>(key_xyz, key_feat,
                                                        query_box, out);
}

// round 7
// speedup vs baseline: 1.0146x; 1.0146x over previous
#include <cuda_runtime.h>

// BoxQueryAndGroup: B=4, N=16384, C=64, NQ=256, S=32
//
// Reference: idx_f = in_box * arange(N); stable argsort ascending, first 32.
// Zero-keys = {n : !in_box[n]} ∪ {0}; answer = 32 smallest indices with
// (n==0 || !in_box), ascending. Fallback loops keep exact argsort semantics
// if fewer than 32 zero-keys exist (statistically impossible here).
// local_group_mask is identically False => 0.0f.
//
// Outputs concatenated flat, float32:
//   grouped_xyz (B,3,NQ,S), new_features (B,67,NQ,S), mask (B,NQ,S)
//
// R6: warp 0 scans points 0..63 -> s_idx; warps 1-7 CONCURRENTLY stage the
// feature window feat[c][0..63] (all 64 ch) into smem. Post-barrier gathers
// are conflict-free LDS (row stride 65 => bank = (c+i) mod 32, all 32 lanes
// distinct). Global-gather fallback if any selected idx >= 64.

#define BQ_B  4
#define BQ_N  16384
#define BQ_C  64
#define BQ_NQ 256
#define BQ_S  32

#define BQ_THREADS 256
#define FW 64            // feature window (points 0..63)
#define FPAD 65          // smem row stride (conflict-free)

__global__ __launch_bounds__(BQ_THREADS)
void boxquery_group_kernel(const float* __restrict__ key_xyz,     // (B,N,3)
                           const float* __restrict__ key_feat,    // (B,C,N)
                           const float* __restrict__ query_box,   // (B,NQ,6)
                           float* __restrict__ out) {
    const int lane = threadIdx.x & 31;
    const int role = threadIdx.x >> 5;          // warp id 0..7
    const int qid  = blockIdx.x;                // b*NQ + q
    const int b    = qid >> 8;
    const int q    = qid & (BQ_NQ - 1);

    __shared__ float s_feat[BQ_C][FPAD];        // 16.6 KB
    __shared__ int   s_idx[BQ_S];
    __shared__ int   s_max;

    const float* qb   = query_box + (size_t)qid * 6;
    const float* xyzb = key_xyz + (size_t)b * BQ_N * 3;
    const float* fb   = key_feat + (size_t)b * BQ_C * BQ_N;

    const float cx = qb[0], cy = qb[1], cz = qb[2];
    const float hx = 0.5f * qb[3], hy = 0.5f * qb[4], hz = 0.5f * qb[5];

    if (role != 0) {
        // ---- Stage feature window into smem (warps 1-7, coalesced) ----
        // 64 rows x 16 float4 = 1024 float4 over 224 threads.
        const int t = threadIdx.x - 32;         // 0..223
        #pragma unroll
        for (int i = t; i < BQ_C * (FW / 4); i += BQ_THREADS - 32) {
            const int c    = i >> 4;            // channel
            const int part = i & 15;            // float4 within row
            const float4 v = *(const float4*)(fb + (size_t)c * BQ_N + part * 4);
            s_feat[c][part * 4 + 0] = v.x;
            s_feat[c][part * 4 + 1] = v.y;
            s_feat[c][part * 4 + 2] = v.z;
            s_feat[c][part * 4 + 3] = v.w;
        }
    } else {
        // ---- Selection scan: warp 0, unrolled 64-point fast path ----
        s_idx[lane] = 0;
        __syncwarp();

        const int n1 = lane + 32;
        const float x0 = xyzb[lane * 3 + 0];
        const float y0 = xyzb[lane * 3 + 1];
        const float z0 = xyzb[lane * 3 + 2];
        const float x1 = xyzb[n1 * 3 + 0];
        const float y1 = xyzb[n1 * 3 + 1];
        const float z1 = xyzb[n1 * 3 + 2];

        const bool inb0 = (fabsf(x0 - cx) <= hx) && (fabsf(y0 - cy) <= hy) &&
                          (fabsf(z0 - cz) <= hz);
        const bool inb1 = (fabsf(x1 - cx) <= hx) && (fabsf(y1 - cy) <= hy) &&
                          (fabsf(z1 - cz) <= hz);
        const bool cand0 = (lane == 0) || !inb0;
        const bool cand1 = !inb1;

        const unsigned m0 = __ballot_sync(0xffffffffu, cand0);
        const unsigned m1 = __ballot_sync(0xffffffffu, cand1);
        const int c0 = __popc(m0);
        const int c1 = __popc(m1);

        int idx = -1;
        if (lane < c0) {
            idx = (int)__fns(m0, 0, lane + 1);
        } else if (lane - c0 < c1) {
            idx = 32 + (int)__fns(m1, 0, lane - c0 + 1);
        }
        if (idx >= 0) s_idx[lane] = idx;

        int count = c0 + c1;
        // Slow continuation (statistically never taken): finish zero-keys.
        if (count < BQ_S) {
            int base = 64;
            while (count < BQ_S && base < BQ_N) {
                const int n = base + lane;
                const float x = xyzb[n * 3 + 0];
                const float y = xyzb[n * 3 + 1];
                const float z = xyzb[n * 3 + 2];
                const bool cand = !((fabsf(x - cx) <= hx) &&
                                    (fabsf(y - cy) <= hy) &&
                                    (fabsf(z - cz) <= hz));
                const unsigned m = __ballot_sync(0xffffffffu, cand);
                const int slot = count + __popc(m & ((1u << lane) - 1u));
                if (cand && slot < BQ_S) s_idx[slot] = n;
                count += __popc(m);
                base  += 32;
            }
            // Pass 2: in-box indices n>0, key=n ascending.
            if (count < BQ_S) {
                base = 0;
                while (count < BQ_S && base < BQ_N) {
                    const int n = base + lane;
                    const float x = xyzb[n * 3 + 0];
                    const float y = xyzb[n * 3 + 1];
                    const float z = xyzb[n * 3 + 2];
                    const bool cand = (n != 0) &&
                                      (fabsf(x - cx) <= hx) &&
                                      (fabsf(y - cy) <= hy) &&
                                      (fabsf(z - cz) <= hz);
                    const unsigned m = __ballot_sync(0xffffffffu, cand);
                    const int slot = count + __popc(m & ((1u << lane) - 1u));
                    if (cand && slot < BQ_S) s_idx[slot] = n;
                    count += __popc(m);
                    base  += 32;
                }
            }
        }
        __syncwarp();
        const int mx = __reduce_max_sync(0xffffffffu, s_idx[lane]);
        if (lane == 0) s_max = mx;
    }
    __syncthreads();

    // ---- Consumers ----
    const int j = lane & 7;                 // float4 slot: samples 4j..4j+3
    const int4 iv = ((const int4*)s_idx)[j];
    const int i0 = iv.x, i1 = iv.y, i2 = iv.z, i3 = iv.w;
    const bool windowed = (s_max < FW);

    float* gxyz = out;                                              // (B,3,NQ,S)
    float* nf   = out + (size_t)BQ_B * 3 * BQ_NQ * BQ_S;            // (B,67,NQ,S)
    float* mask = nf  + (size_t)BQ_B * (3 + BQ_C) * BQ_NQ * BQ_S;   // (B,NQ,S)
    const size_t plane = (size_t)BQ_NQ * BQ_S;
    const size_t qs4   = (size_t)q * BQ_S + 4 * j;

    if (role < 2) {
        const int r = lane >> 3;            // 0=gx 1=gy 2=gz 3=mask
        float4 v = make_float4(0.f, 0.f, 0.f, 0.f);
        if (r < 3) {
            const float cr = (r == 0) ? cx : (r == 1) ? cy : cz;
            v.x = xyzb[i0 * 3 + r] - cr;
            v.y = xyzb[i1 * 3 + r] - cr;
            v.z = xyzb[i2 * 3 + r] - cr;
            v.w = xyzb[i3 * 3 + r] - cr;
        }
        if (role == 0) {
            float* p = (r < 3) ? (gxyz + ((size_t)b * 3 + r) * plane + qs4)
                               : (mask + (size_t)b * plane + qs4);
            *(float4*)p = v;
        } else if (r < 3) {
            *(float4*)(nf + ((size_t)b * (3 + BQ_C) + r) * plane + qs4) = v;
        }
    }

    // Features: 8 channels per warp, gathered from smem (fast) or global.
    const int c0ch = role * 8;
    if (windowed) {
        #pragma unroll
        for (int p = 0; p < 2; p++) {
            const int c = c0ch + p * 4 + (lane >> 3);
            float4 v;
            v.x = s_feat[c][i0];
            v.y = s_feat[c][i1];
            v.z = s_feat[c][i2];
            v.w = s_feat[c][i3];
            *(float4*)(nf + ((size_t)b * (3 + BQ_C) + 3 + c) * plane + qs4) = v;
        }
    } else {
        #pragma unroll
        for (int p = 0; p < 2; p++) {
            const int c = c0ch + p * 4 + (lane >> 3);
            const float* fr = fb + (size_t)c * BQ_N;
            float4 v;
            v.x = __ldg(fr + i0);
            v.y = __ldg(fr + i1);
            v.z = __ldg(fr + i2);
            v.w = __ldg(fr + i3);
            *(float4*)(nf + ((size_t)b * (3 + BQ_C) + 3 + c) * plane + qs4) = v;
        }
    }
}

extern "C" void kernel_launch(void* const* d_in, const int* in_sizes, int n_in,
                              void* d_out, int out_size) {
    const float* key_xyz   = (const float*)d_in[0];
    const float* key_feat  = (const float*)d_in[1];
    const float* query_box = (const float*)d_in[2];
    float* out = (float*)d_out;

    boxquery_group_kernel<<<BQ_B * BQ_NQ, BQ_THREADS>>>(key_xyz, key_feat,
                                                        query_box, out);
}

// round 8
// speedup vs baseline: 1.0221x; 1.0074x over previous
#include <cuda_runtime.h>

// BoxQueryAndGroup: B=4, N=16384, C=64, NQ=256, S=32
//
// Reference: idx_f = in_box * arange(N); stable argsort ascending, first 32.
// Zero-keys = {n : !in_box[n]} ∪ {0}; answer = 32 smallest indices with
// (n==0 || !in_box), ascending. Slow loops keep exact argsort semantics if
// fewer than 32 zero-keys exist (statistically impossible here).
// local_group_mask is identically False => 0.0f.
//
// Outputs concatenated flat, float32:
//   grouped_xyz (B,3,NQ,S), new_features (B,67,NQ,S), mask (B,NQ,S)
//
// R7: ONE WARP PER QUERY does scan + all output. No smem, no __syncthreads,
// no inter-warp coupling. Indices live in registers (ballot + __fns + shfl).
// Each thread owns float4 slot j=lane&7 and row group lane>>3; 16 feature
// passes + 1 xyz/mask pass, all STG.128. Warps de-phase freely.

#define BQ_B  4
#define BQ_N  16384
#define BQ_C  64
#define BQ_NQ 256
#define BQ_S  32

#define BQ_BLOCK 128     // 4 independent warps per block

__global__ __launch_bounds__(BQ_BLOCK)
void boxquery_group_kernel(const float* __restrict__ key_xyz,     // (B,N,3)
                           const float* __restrict__ key_feat,    // (B,C,N)
                           const float* __restrict__ query_box,   // (B,NQ,6)
                           float* __restrict__ out) {
    const int lane = threadIdx.x & 31;
    const int wq   = blockIdx.x * (BQ_BLOCK / 32) + (threadIdx.x >> 5); // query 0..1023
    const int b    = wq >> 8;
    const int q    = wq & (BQ_NQ - 1);

    const float* qb   = query_box + (size_t)wq * 6;
    const float* xyzb = key_xyz + (size_t)b * BQ_N * 3;
    const float* fb   = key_feat + (size_t)b * BQ_C * BQ_N;

    const float cx = qb[0], cy = qb[1], cz = qb[2];
    const float hx = 0.5f * qb[3], hy = 0.5f * qb[4], hz = 0.5f * qb[5];

    // ---- Selection scan: unrolled 64-point fast path, in-register ----
    int idx = 0;   // idx_sorted[lane]
    {
        const int n1 = lane + 32;
        const float x0 = xyzb[lane * 3 + 0];
        const float y0 = xyzb[lane * 3 + 1];
        const float z0 = xyzb[lane * 3 + 2];
        const float x1 = xyzb[n1 * 3 + 0];
        const float y1 = xyzb[n1 * 3 + 1];
        const float z1 = xyzb[n1 * 3 + 2];

        const bool inb0 = (fabsf(x0 - cx) <= hx) && (fabsf(y0 - cy) <= hy) &&
                          (fabsf(z0 - cz) <= hz);
        const bool inb1 = (fabsf(x1 - cx) <= hx) && (fabsf(y1 - cy) <= hy) &&
                          (fabsf(z1 - cz) <= hz);
        const bool cand0 = (lane == 0) || !inb0;
        const bool cand1 = !inb1;

        const unsigned m0 = __ballot_sync(0xffffffffu, cand0);
        const unsigned m1 = __ballot_sync(0xffffffffu, cand1);
        const int c0 = __popc(m0);
        const int c1 = __popc(m1);

        if (c0 + c1 >= BQ_S) {
            // All 32 slots resolved within points 0..63.
            idx = (lane < c0) ? (int)__fns(m0, 0, lane + 1)
                              : 32 + (int)__fns(m1, 0, lane - c0 + 1);
        } else {
            // Slow path (statistically never taken): exact argsort semantics.
            int count = 0, base = 0;
            // Pass 1: zero-keys ascending.
            while (count < BQ_S && base < BQ_N) {
                const int n = base + lane;
                const float x = xyzb[n * 3 + 0];
                const float y = xyzb[n * 3 + 1];
                const float z = xyzb[n * 3 + 2];
                const bool inb = (fabsf(x - cx) <= hx) &&
                                 (fabsf(y - cy) <= hy) &&
                                 (fabsf(z - cz) <= hz);
                const bool cand = (n == 0) || !inb;
                const unsigned m = __ballot_sync(0xffffffffu, cand);
                const int pc = __popc(m);
                if (lane >= count && lane < count + pc)
                    idx = base + (int)__fns(m, 0, lane - count + 1);
                count += pc;
                base  += 32;
            }
            // Pass 2: in-box indices n>0, key=n ascending.
            if (count < BQ_S) {
                base = 0;
                while (count < BQ_S && base < BQ_N) {
                    const int n = base + lane;
                    const float x = xyzb[n * 3 + 0];
                    const float y = xyzb[n * 3 + 1];
                    const float z = xyzb[n * 3 + 2];
                    const bool cand = (n != 0) &&
                                      (fabsf(x - cx) <= hx) &&
                                      (fabsf(y - cy) <= hy) &&
                                      (fabsf(z - cz) <= hz);
                    const unsigned m = __ballot_sync(0xffffffffu, cand);
                    const int pc = __popc(m);
                    if (lane >= count && lane < count + pc)
                        idx = base + (int)__fns(m, 0, lane - count + 1);
                    count += pc;
                    base  += 32;
                }
            }
        }
    }

    // Distribute: thread owns float4 slot j (samples 4j..4j+3).
    const int j = lane & 7;
    const int g = lane >> 3;     // row-group 0..3
    const int i0 = __shfl_sync(0xffffffffu, idx, 4 * j + 0);
    const int i1 = __shfl_sync(0xffffffffu, idx, 4 * j + 1);
    const int i2 = __shfl_sync(0xffffffffu, idx, 4 * j + 2);
    const int i3 = __shfl_sync(0xffffffffu, idx, 4 * j + 3);

    // Output sections
    float* gxyz = out;                                              // (B,3,NQ,S)
    float* nf   = out + (size_t)BQ_B * 3 * BQ_NQ * BQ_S;            // (B,67,NQ,S)
    float* mask = nf  + (size_t)BQ_B * (3 + BQ_C) * BQ_NQ * BQ_S;   // (B,NQ,S)
    const size_t plane = (size_t)BQ_NQ * BQ_S;
    const size_t qs4   = (size_t)q * BQ_S + 4 * j;

    float* nfq = nf + (size_t)b * (3 + BQ_C) * plane + qs4;

    // ---- xyz rows (0..2) + mask ----
    {
        float4 v = make_float4(0.f, 0.f, 0.f, 0.f);
        if (g < 3) {
            const float cr = (g == 0) ? cx : (g == 1) ? cy : cz;
            v.x = xyzb[i0 * 3 + g] - cr;
            v.y = xyzb[i1 * 3 + g] - cr;
            v.z = xyzb[i2 * 3 + g] - cr;
            v.w = xyzb[i3 * 3 + g] - cr;
            *(float4*)(gxyz + ((size_t)b * 3 + g) * plane + qs4) = v;
            *(float4*)(nfq + (size_t)g * plane) = v;
        } else {
            *(float4*)(mask + (size_t)b * plane + qs4) = v;  // mask == 0
        }
    }

    // ---- Feature rows: 16 passes, channel c = 4p + g ----
    const float* fr = fb + (size_t)g * BQ_N;
    float*       po = nfq + (size_t)(3 + g) * plane;
    #pragma unroll 4
    for (int p = 0; p < 16; p++) {
        float4 v;
        v.x = __ldg(fr + i0);
        v.y = __ldg(fr + i1);
        v.z = __ldg(fr + i2);
        v.w = __ldg(fr + i3);
        *(float4*)po = v;
        fr += 4 * BQ_N;
        po += 4 * plane;
    }
}

extern "C" void kernel_launch(void* const* d_in, const int* in_sizes, int n_in,
                              void* d_out, int out_size) {
    const float* key_xyz   = (const float*)d_in[0];
    const float* key_feat  = (const float*)d_in[1];
    const float* query_box = (const float*)d_in[2];
    float* out = (float*)d_out;

    // One warp per query: 1024 warps = 256 blocks x 4 warps.
    boxquery_group_kernel<<<(BQ_B * BQ_NQ) / (BQ_BLOCK / 32), BQ_BLOCK>>>(
        key_xyz, key_feat, query_box, out);
}